// round 6
// baseline (speedup 1.0000x reference)
#include <cuda_runtime.h>

#define THREADS 256
#define Jt 32
#define NT 32          // 1024 / Jt

typedef unsigned long long u64;
typedef unsigned int u32;

__device__ __forceinline__ float tanh_apx(float x) {
    float r; asm("tanh.approx.f32 %0, %1;" : "=f"(r) : "f"(x)); return r;
}
__device__ __forceinline__ float rcp_apx(float x) {
    float r; asm("rcp.approx.f32 %0, %1;" : "=f"(r) : "f"(x)); return r;
}
#define FMA2(d,a,b,c)  asm("fma.rn.f32x2 %0, %1, %2, %3;" : "=l"(d) : "l"(a), "l"(b), "l"(c))
#define ADD2(d,a,b)    asm("add.rn.f32x2 %0, %1, %2;" : "=l"(d) : "l"(a), "l"(b))
#define PACK2(d,x,y)   asm("mov.b64 %0, {%1,%2};" : "=l"(d) : "f"(x), "f"(y))
#define UNPACK2(x,y,d) asm("mov.b64 {%0,%1}, %2;" : "=f"(x), "=f"(y) : "l"(d))

#define LOG2E 1.4426950408889634f
#define LN2   0.6931471805599453f
#define MAGICF 12582912.0f            // 1.5 * 2^23

__global__ __launch_bounds__(THREADS, 3)
void attn_mlp_kernel(const float* __restrict__ Q, const float* __restrict__ K,
                     const float* __restrict__ bias, const float* __restrict__ mask,
                     float* __restrict__ out, float* __restrict__ attn)
{
    __shared__ float4 ksm[2][Jt * 17];   // double-buffered K tile (17.4 KB)
    __shared__ float  red[1024];         // [warp][row][ch]
    __shared__ float  cbuf[2][8];

    const int tid = threadIdx.x;
    const int w   = tid >> 5, l = tid & 31;
    const int cg  = l & 7;               // channel group: 8 channels
    const int jw  = l >> 3;              // j within warp (0..3)
    const int jl  = w * 4 + jw;          // j within tile (0..31)

    const int row0 = blockIdx.x * 2;     // two i-rows per block, same b
    const int b    = row0 >> 10;

    // pair p=0 -> tanh path (prescale 0.5: sigma = 0.5+0.5*tanh(x/2))
    // pairs p=1..3 -> poly path (prescale -log2e: sigma = 1/(1+2^s), s=-log2e*x)
    u64 q0[4], q1[4], bb[4], s0[4], s1[4];
    {
        const float* q0p = Q + (size_t)row0 * 64 + cg * 8;
        const float* q1p = q0p + 64;
        const float* bp  = bias + cg * 8;
#pragma unroll
        for (int p = 0; p < 4; ++p) {
            float sc = (p == 0) ? 0.5f : -LOG2E;
            PACK2(q0[p], sc * q0p[2*p], sc * q0p[2*p+1]);
            PACK2(q1[p], sc * q1p[2*p], sc * q1p[2*p+1]);
            PACK2(bb[p], sc * bp[2*p],  sc * bp[2*p+1]);
            s0[p] = 0ull; s1[p] = 0ull;
        }
    }
    float cnt0 = 0.f, cnt1 = 0.f;

    u64 MG2, NEG1, C1p, C2p, C3p;
    PACK2(MG2,  MAGICF, MAGICF);
    PACK2(NEG1, -1.0f, -1.0f);
    PACK2(C1p, 0.69314718f, 0.69314718f);
    PACK2(C2p, 0.24013972f, 0.24013972f);
    PACK2(C3p, 0.05582818f, 0.05582818f);
    u64 ONE2; PACK2(ONE2, 1.0f, 1.0f);

    const float4* Kg  = (const float4*)K + (size_t)b * 1024 * 16;
    const float*  m0p = mask + (size_t)row0 * 1024;
    const float*  m1p = m0p + 1024;
    float*        a0p = attn + (size_t)row0 * 1024;
    float*        a1p = a0p + 1024;

    // prefetch tile 0 (512 float4 / 256 threads = 2 each)
    const int f0 = tid, f1 = tid + 256;
    float4 kpre0 = Kg[(size_t)(f0 >> 4) * 16 + (f0 & 15)];
    float4 kpre1 = Kg[(size_t)(f1 >> 4) * 16 + (f1 & 15)];

    int buf = 0;
    for (int tile = 0; tile < NT; ++tile) {
        ksm[buf][(f0 >> 4) * 17 + (f0 & 15)] = kpre0;
        ksm[buf][(f1 >> 4) * 17 + (f1 & 15)] = kpre1;
        __syncthreads();

        if (tile + 1 < NT) {
            kpre0 = Kg[(size_t)((tile + 1) * Jt + (f0 >> 4)) * 16 + (f0 & 15)];
            kpre1 = Kg[(size_t)((tile + 1) * Jt + (f1 >> 4)) * 16 + (f1 & 15)];
        }

        const int   j  = tile * Jt + jl;
        const float m0 = m0p[j], m1 = m1p[j];

        const u64* kb = (const u64*)(ksm[buf]) + jl * 34 + cg * 4;  // 8 channels
        u64 k2[4];
#pragma unroll
        for (int p = 0; p < 4; ++p) k2[p] = kb[p];

        u64 m20, m21; PACK2(m20, m0, m0); PACK2(m21, m1, m1);
        u64 dA0 = 0ull, dA1 = 0ull;   // tanh-path dot partials (scale 0.5)
        u64 dB0 = 0ull, dB1 = 0ull;   // poly-path dot partials (scale -log2e)

#pragma unroll
        for (int p = 0; p < 4; ++p) {
            if (p == 0) {
                // ---- tanh path ----
                u64 l2, t2; float la, lb;
                FMA2(l2, q0[p], k2[p], bb[p]);
                FMA2(dA0, q0[p], k2[p], dA0);
                UNPACK2(la, lb, l2);
                PACK2(t2, tanh_apx(la), tanh_apx(lb));
                FMA2(s0[p], m20, t2, s0[p]);

                FMA2(l2, q1[p], k2[p], bb[p]);
                FMA2(dA1, q1[p], k2[p], dA1);
                UNPACK2(la, lb, l2);
                PACK2(t2, tanh_apx(la), tanh_apx(lb));
                FMA2(s1[p], m21, t2, s1[p]);
            } else {
                // ---- poly-exp2 path: s = -log2e*(qk+b); sigma = 1/(1+2^s)
#pragma unroll
                for (int r = 0; r < 2; ++r) {
                    u64 qq = r ? q1[p] : q0[p];
                    u64 s2, t2, i2, f2, y2;
                    FMA2(s2, qq, k2[p], bb[p]);
                    if (r) { FMA2(dB1, qq, k2[p], dB1); }
                    else   { FMA2(dB0, qq, k2[p], dB0); }
                    ADD2(t2, s2, MG2);               // t = s + M  (round-to-int trick)
                    FMA2(i2, MG2, NEG1, t2);         // i = t - M  (exact)
                    FMA2(f2, i2, NEG1, s2);          // f = s - i, in [-0.5, 0.5]
                    FMA2(y2, C3p, f2, C2p);          // Horner 2^f
                    FMA2(y2, y2, f2, C1p);
                    FMA2(y2, y2, f2, ONE2);
                    float tl, th, yl, yh;
                    UNPACK2(tl, th, t2);
                    UNPACK2(yl, yh, y2);
                    u32 pl = __float_as_uint(tl) * 8388608u + __float_as_uint(yl); // y*2^i
                    u32 ph = __float_as_uint(th) * 8388608u + __float_as_uint(yh);
                    float dl = __uint_as_float(pl) + 1.0f;
                    float dh = __uint_as_float(ph) + 1.0f;
                    u64 g2; PACK2(g2, rcp_apx(dl), rcp_apx(dh));
                    if (r) { FMA2(s1[p], m21, g2, s1[p]); }
                    else   { FMA2(s0[p], m20, g2, s0[p]); }
                }
            }
        }
        cnt0 += m0; cnt1 += m1;      // every lane; 8x-dup resolved in reduction

        // attention logits: Q.K = 2*dA - ln2*dB  (exact fp32 path)
        float ax, ay, bx, by;
        UNPACK2(ax, ay, dA0); UNPACK2(bx, by, dB0);
        float d0 = 2.0f * (ax + ay) - LN2 * (bx + by);
        UNPACK2(ax, ay, dA1); UNPACK2(bx, by, dB1);
        float d1 = 2.0f * (ax + ay) - LN2 * (bx + by);
        d0 += __shfl_xor_sync(~0u, d0, 1);
        d0 += __shfl_xor_sync(~0u, d0, 2);
        d0 += __shfl_xor_sync(~0u, d0, 4);
        d1 += __shfl_xor_sync(~0u, d1, 1);
        d1 += __shfl_xor_sync(~0u, d1, 2);
        d1 += __shfl_xor_sync(~0u, d1, 4);
        if (cg == 0) {
            a0p[j] = d0 * m0;
            a1p[j] = d1 * m1;
        }
        buf ^= 1;
    }

    // ---- final reductions ----
    // sum accumulators over the 4 jw lanes (xor 8,16); lanes with jw==0 write
#pragma unroll
    for (int p = 0; p < 4; ++p) {
        float x0, y0, x1, y1;
        UNPACK2(x0, y0, s0[p]); UNPACK2(x1, y1, s1[p]);
#pragma unroll
        for (int o = 8; o <= 16; o <<= 1) {
            x0 += __shfl_xor_sync(~0u, x0, o);
            y0 += __shfl_xor_sync(~0u, y0, o);
            x1 += __shfl_xor_sync(~0u, x1, o);
            y1 += __shfl_xor_sync(~0u, y1, o);
        }
        if (jw == 0) {
            float* rp = red + w * 128 + cg * 8 + 2 * p;
            rp[0]      = x0;
            rp[1]      = y0;
            rp[64]     = x1;
            rp[64 + 1] = y1;
        }
    }
    // mask counts: each j's mask duplicated across 8 cg lanes; xor 8,16 sums 4 jw
    cnt0 += __shfl_xor_sync(~0u, cnt0, 8);
    cnt0 += __shfl_xor_sync(~0u, cnt0, 16);
    cnt1 += __shfl_xor_sync(~0u, cnt1, 8);
    cnt1 += __shfl_xor_sync(~0u, cnt1, 16);
    if (l == 0) { cbuf[0][w] = cnt0; cbuf[1][w] = cnt1; }
    __syncthreads();

    if (tid < 128) {
        const int r  = tid >> 6;
        const int ch = tid & 63;
        float ct = 0.f, s = 0.f;
#pragma unroll
        for (int ww = 0; ww < 8; ++ww) {
            ct += cbuf[r][ww];
            s  += red[ww * 128 + r * 64 + ch];
        }
        // pair p = (ch&7)>>1: p==0 tanh (0.5+0.5*s/ct), else poly (s/ct)
        float v = (((ch & 7) >> 1) == 0) ? (0.5f + 0.5f * s / ct) : (s / ct);
        out[(size_t)(row0 + r) * 64 + ch] = v;
    }
}

extern "C" void kernel_launch(void* const* d_in, const int* in_sizes, int n_in,
                              void* d_out, int out_size)
{
    const float* Q    = (const float*)d_in[0];
    const float* K    = (const float*)d_in[1];
    const float* bias = (const float*)d_in[2];
    const float* mask = (const float*)d_in[3];
    float* out  = (float*)d_out;                       // [B, I, C]
    float* attn = out + (size_t)2 * 1024 * 64;         // [B, I, J]
    attn_mlp_kernel<<<1024, THREADS>>>(Q, K, bias, mask, out, attn);
}

// round 7
// speedup vs baseline: 1.3085x; 1.3085x over previous
#include <cuda_runtime.h>

#define THREADS 128
#define Jt 32
#define NT 32          // 1024 / Jt

typedef unsigned long long u64;
typedef unsigned int u32;

__device__ __forceinline__ float tanh_apx(float x) {
    float r; asm("tanh.approx.f32 %0, %1;" : "=f"(r) : "f"(x)); return r;
}
#define FMA2(d,a,b,c)  asm("fma.rn.f32x2 %0, %1, %2, %3;" : "=l"(d) : "l"(a), "l"(b), "l"(c))
#define PACK2(d,x,y)   asm("mov.b64 %0, {%1,%2};" : "=l"(d) : "f"(x), "f"(y))
#define UNPACK2(x,y,d) asm("mov.b64 {%0,%1}, %2;" : "=f"(x), "=f"(y) : "l"(d))

__global__ __launch_bounds__(THREADS, 5)
void attn_mlp_kernel(const float* __restrict__ Q, const float* __restrict__ K,
                     const float* __restrict__ bias, const float* __restrict__ mask,
                     float* __restrict__ out, float* __restrict__ attn)
{
    __shared__ float4 ksm[2][Jt * 17];   // double-buffered K tile, pad 17 -> conflict-free
    __shared__ float  red[4 * 64];       // [warp][ch]
    __shared__ float  cbuf[4];

    const int tid = threadIdx.x;
    const int w   = tid >> 5, l = tid & 31;
    const int jl  = w * 8 + (l & 7);     // j within tile (0..31)
    const int cg  = l >> 3;              // channel group (16 ch each)

    const int row = blockIdx.x;          // one i-row per block
    const int b   = row >> 10;

    // prescaled q (x0.5: sigmoid = 0.5 + 0.5*tanh(x/2)) and bias, packed f32x2
    u64 q2[8], b2[8], s2[8];
    {
        const float* qp = Q + (size_t)row * 64 + cg * 16;
        const float* bp = bias + cg * 16;
#pragma unroll
        for (int p = 0; p < 8; ++p) {
            PACK2(q2[p], 0.5f * qp[2*p], 0.5f * qp[2*p+1]);
            PACK2(b2[p], 0.5f * bp[2*p], 0.5f * bp[2*p+1]);
            s2[p] = 0ull;
        }
    }
    float cnt = 0.f;

    const float4* Kg   = (const float4*)K + (size_t)b * 1024 * 16;
    const float*  mrow = mask + (size_t)row * 1024;
    float*        arow = attn + (size_t)row * 1024;

    // prefetch tile 0 into registers (4 float4/thread)
    float4 kpre[4];
#pragma unroll
    for (int u = 0; u < 4; ++u) {
        int f = u * 128 + tid;
        kpre[u] = Kg[(size_t)(f >> 4) * 16 + (f & 15)];
    }

    int buf = 0;
    for (int tile = 0; tile < NT; ++tile) {
#pragma unroll
        for (int u = 0; u < 4; ++u) {
            int f = u * 128 + tid;
            ksm[buf][(f >> 4) * 17 + (f & 15)] = kpre[u];
        }
        __syncthreads();

        if (tile + 1 < NT) {
#pragma unroll
            for (int u = 0; u < 4; ++u) {
                int f = u * 128 + tid;
                kpre[u] = Kg[(size_t)((tile + 1) * Jt + (f >> 4)) * 16 + (f & 15)];
            }
        }

        // 16 channels for this thread's j, straight from padded smem as u64 pairs
        const u64* kb = (const u64*)(ksm[buf]) + jl * 34 + cg * 8;
        u64 k2[8];
#pragma unroll
        for (int p = 0; p < 8; ++p) k2[p] = kb[p];

        const int   j = tile * Jt + jl;
        const float m = mrow[j];
        u64 m2; PACK2(m2, m, m);
        u64 dp = 0ull;

#pragma unroll
        for (int p = 0; p < 8; ++p) {
            u64 l2, t2; float la, lb;
            FMA2(l2, q2[p], k2[p], b2[p]);
            FMA2(dp, q2[p], k2[p], dp);
            UNPACK2(la, lb, l2);
            PACK2(t2, tanh_apx(la), tanh_apx(lb));
            FMA2(s2[p], m2, t2, s2[p]);
        }
        cnt += m;      // every lane; 4x cg duplication fixed by 0.25 at the end

        // attention logits: q prescaled by 0.5 -> attn = 2*dot*mask (exact fp32 path)
        float dx, dy;
        UNPACK2(dx, dy, dp);
        float d = dx + dy;
        d += __shfl_xor_sync(~0u, d, 8);
        d += __shfl_xor_sync(~0u, d, 16);
        if (cg == 0)
            arow[j] = (d + d) * m;

        buf ^= 1;
    }

    // ---- final reductions ----
    // sum accumulators over the 8 j-lanes sharing this cg (xor 1,2,4)
#pragma unroll
    for (int p = 0; p < 8; ++p) {
        float x, y;
        UNPACK2(x, y, s2[p]);
#pragma unroll
        for (int o = 1; o <= 4; o <<= 1) {
            x += __shfl_xor_sync(~0u, x, o);
            y += __shfl_xor_sync(~0u, y, o);
        }
        if ((l & 7) == 0) {
            float* rp = red + w * 64 + cg * 16 + 2 * p;
            rp[0] = x;
            rp[1] = y;
        }
    }
    // mask count: full-warp sum counts each j 4x (once per cg lane)
#pragma unroll
    for (int o = 1; o <= 16; o <<= 1)
        cnt += __shfl_xor_sync(~0u, cnt, o);
    if (l == 0) cbuf[w] = cnt;
    __syncthreads();

    if (tid < 64) {
        float ct = 0.25f * (cbuf[0] + cbuf[1] + cbuf[2] + cbuf[3]);
        float s  = red[tid] + red[64 + tid] + red[128 + tid] + red[192 + tid];
        out[(size_t)row * 64 + tid] = 0.5f + 0.5f * s / ct;
    }
}

extern "C" void kernel_launch(void* const* d_in, const int* in_sizes, int n_in,
                              void* d_out, int out_size)
{
    const float* Q    = (const float*)d_in[0];
    const float* K    = (const float*)d_in[1];
    const float* bias = (const float*)d_in[2];
    const float* mask = (const float*)d_in[3];
    float* out  = (float*)d_out;                       // [B, I, C]
    float* attn = out + (size_t)2 * 1024 * 64;         // [B, I, J]
    attn_mlp_kernel<<<2048, THREADS>>>(Q, K, bias, mask, out, attn);
}

// round 8
// speedup vs baseline: 1.7499x; 1.3373x over previous
#include <cuda_runtime.h>

#define THREADS 128
#define Jt 32
#define NT 32          // 1024 / Jt

typedef unsigned long long u64;
typedef unsigned int u32;

#define FMA2(d,a,b,c)  asm("fma.rn.f32x2 %0, %1, %2, %3;" : "=l"(d) : "l"(a), "l"(b), "l"(c))
#define PACK2(d,x,y)   asm("mov.b64 %0, {%1,%2};" : "=l"(d) : "f"(x), "f"(y))
#define UNPACK2(x,y,d) asm("mov.b64 {%0,%1}, %2;" : "=f"(x), "=f"(y) : "l"(d))

// two f32 -> f16x2 (lo = la, hi = lb), tanh on both halves in ONE MUFU inst,
// back to two f32
__device__ __forceinline__ void tanh2_f16(float la, float lb, float& ta, float& tb) {
    u32 h, th;
    asm("cvt.rn.f16x2.f32 %0, %1, %2;" : "=r"(h) : "f"(lb), "f"(la));   // first src -> hi
    asm("tanh.approx.f16x2 %0, %1;" : "=r"(th) : "r"(h));
    asm("{ .reg .f16 lo, hi;\n\t"
        "  mov.b32 {lo, hi}, %2;\n\t"
        "  cvt.f32.f16 %0, lo;\n\t"
        "  cvt.f32.f16 %1, hi; }"
        : "=f"(ta), "=f"(tb) : "r"(th));
}

__global__ __launch_bounds__(THREADS, 3)
void attn_mlp_kernel(const float* __restrict__ Q, const float* __restrict__ K,
                     const float* __restrict__ bias, const float* __restrict__ mask,
                     float* __restrict__ out, float* __restrict__ attn)
{
    __shared__ float4 ksm[2][Jt * 17];   // double-buffered K tile, pad 17 -> conflict-free
    __shared__ float  red[512];
    __shared__ float  cbuf[2][4];

    const int tid = threadIdx.x;
    const int w   = tid >> 5, l = tid & 31;
    const int jl  = w * 8 + (l & 7);     // j within tile (0..31)
    const int cg  = l >> 3;              // channel group (16 ch each)

    const int row0 = blockIdx.x * 2;     // two i-rows per block, same b
    const int b    = row0 >> 10;

    // q prescaled by 0.5 (sigmoid = 0.5 + 0.5*tanh(x/2)), bias likewise; f32x2 packed
    u64 q20[8], q21[8], b2[8], s20[8], s21[8];
    {
        const float* q0p = Q + (size_t)row0 * 64 + cg * 16;
        const float* q1p = q0p + 64;
        const float* bp  = bias + cg * 16;
#pragma unroll
        for (int p = 0; p < 8; ++p) {
            PACK2(q20[p], 0.5f * q0p[2*p], 0.5f * q0p[2*p+1]);
            PACK2(q21[p], 0.5f * q1p[2*p], 0.5f * q1p[2*p+1]);
            PACK2(b2[p],  0.5f * bp[2*p],  0.5f * bp[2*p+1]);
            s20[p] = 0ull; s21[p] = 0ull;
        }
    }
    float cnt0 = 0.f, cnt1 = 0.f;

    const float4* Kg  = (const float4*)K + (size_t)b * 1024 * 16;
    const float*  m0p = mask + (size_t)row0 * 1024;
    const float*  m1p = m0p + 1024;
    float*        a0p = attn + (size_t)row0 * 1024;
    float*        a1p = a0p + 1024;

    // prefetch tile 0 into registers
    float4 kpre[4];
#pragma unroll
    for (int u = 0; u < 4; ++u) {
        int f = u * 128 + tid;
        kpre[u] = Kg[(size_t)(f >> 4) * 16 + (f & 15)];
    }

    int buf = 0;
    for (int tile = 0; tile < NT; ++tile) {
#pragma unroll
        for (int u = 0; u < 4; ++u) {
            int f = u * 128 + tid;
            ksm[buf][(f >> 4) * 17 + (f & 15)] = kpre[u];
        }
        __syncthreads();

        if (tile + 1 < NT) {
#pragma unroll
            for (int u = 0; u < 4; ++u) {
                int f = u * 128 + tid;
                kpre[u] = Kg[(size_t)((tile + 1) * Jt + (f >> 4)) * 16 + (f & 15)];
            }
        }

        u64 k2[8];
#pragma unroll
        for (int p4 = 0; p4 < 4; ++p4) {
            float4 kv = ksm[buf][jl * 17 + cg * 4 + p4];
            PACK2(k2[2*p4],   kv.x, kv.y);
            PACK2(k2[2*p4+1], kv.z, kv.w);
        }
        const int   j  = tile * Jt + jl;
        const float m0 = m0p[j], m1 = m1p[j];
        u64 m20, m21; PACK2(m20, m0, m0); PACK2(m21, m1, m1);
        u64 dp0 = 0ull, dp1 = 0ull;

#pragma unroll
        for (int p = 0; p < 8; ++p) {
            u64 l2, t2; float la, lb, ta, tb;
            // row 0
            FMA2(l2, q20[p], k2[p], b2[p]);      // f32 logit (prescaled 0.5)
            FMA2(dp0, q20[p], k2[p], dp0);       // f32 dot partial (exact attn path)
            UNPACK2(la, lb, l2);
            tanh2_f16(la, lb, ta, tb);           // ONE MUFU inst for both channels
            PACK2(t2, ta, tb);
            FMA2(s20[p], m20, t2, s20[p]);
            // row 1
            FMA2(l2, q21[p], k2[p], b2[p]);
            FMA2(dp1, q21[p], k2[p], dp1);
            UNPACK2(la, lb, l2);
            tanh2_f16(la, lb, ta, tb);
            PACK2(t2, ta, tb);
            FMA2(s21[p], m21, t2, s21[p]);
        }
        if (cg == 0) { cnt0 += m0; cnt1 += m1; }

        // attention logits: q prescaled by 0.5 -> attn = 2*dot*mask (exact fp32 path)
        float dx, dy;
        UNPACK2(dx, dy, dp0); float d0 = dx + dy;
        UNPACK2(dx, dy, dp1); float d1 = dx + dy;
        d0 += __shfl_xor_sync(~0u, d0, 8);
        d0 += __shfl_xor_sync(~0u, d0, 16);
        d1 += __shfl_xor_sync(~0u, d1, 8);
        d1 += __shfl_xor_sync(~0u, d1, 16);
        if (cg == 0) {
            a0p[j] = (d0 + d0) * m0;
            a1p[j] = (d1 + d1) * m1;
        }
        buf ^= 1;
    }

    // ---- final reductions ----
#pragma unroll
    for (int p = 0; p < 8; ++p) {
        float x0, y0, x1, y1;
        UNPACK2(x0, y0, s20[p]); UNPACK2(x1, y1, s21[p]);
#pragma unroll
        for (int o = 1; o <= 4; o <<= 1) {
            x0 += __shfl_xor_sync(~0u, x0, o);
            y0 += __shfl_xor_sync(~0u, y0, o);
            x1 += __shfl_xor_sync(~0u, x1, o);
            y1 += __shfl_xor_sync(~0u, y1, o);
        }
        if ((l & 7) == 0) {
            float* rp = red + w * 128 + cg * 32;
            rp[2*p]          = x0;
            rp[2*p + 1]      = y0;
            rp[16 + 2*p]     = x1;
            rp[16 + 2*p + 1] = y1;
        }
    }
    for (int o = 1; o <= 4; o <<= 1) {
        cnt0 += __shfl_xor_sync(~0u, cnt0, o);
        cnt1 += __shfl_xor_sync(~0u, cnt1, o);
    }
    if (l == 0) { cbuf[0][w] = cnt0; cbuf[1][w] = cnt1; }
    __syncthreads();

    {
        const int r  = tid >> 6;
        const int ch = tid & 63;
        float ct = cbuf[r][0] + cbuf[r][1] + cbuf[r][2] + cbuf[r][3];
        float s  = 0.f;
#pragma unroll
        for (int ww = 0; ww < 4; ++ww)
            s += red[ww * 128 + (ch >> 4) * 32 + r * 16 + (ch & 15)];
        out[(size_t)(row0 + r) * 64 + ch] = 0.5f + 0.5f * s / ct;
    }
}

extern "C" void kernel_launch(void* const* d_in, const int* in_sizes, int n_in,
                              void* d_out, int out_size)
{
    const float* Q    = (const float*)d_in[0];
    const float* K    = (const float*)d_in[1];
    const float* bias = (const float*)d_in[2];
    const float* mask = (const float*)d_in[3];
    float* out  = (float*)d_out;                       // [B, I, C]
    float* attn = out + (size_t)2 * 1024 * 64;         // [B, I, J]
    attn_mlp_kernel<<<1024, THREADS>>>(Q, K, bias, mask, out, attn);
}